// round 2
// baseline (speedup 1.0000x reference)
#include <cuda_runtime.h>
#include <cuda_bf16.h>

// PositionalEmbedding: out[b, flat] = x[b, flat] + pe_flat[flat mod 2^20],
// pe computed in [h, w, ch] order, raw-reshaped onto [ch, h, w].
// B=32, C=256, H=64, W=64.
//
// Key structural fact: with exactly 2^20 threads, a grid-stride of 2^20
// float4s = 4*M_BATCH elements, so (t mod M_BATCH) — and therefore the pe
// float4 — is INVARIANT across a thread's iterations. Compute pe once,
// then pure stream: 8x { LDG.128, 4 FADD, STG.128 }.

#define B_DIM 32
#define C_DIM 256
#define H_DIM 64
#define W_DIM 64

#define N_TOTAL (B_DIM * C_DIM * H_DIM * W_DIM)   // 33,554,432
#define M_BATCH (C_DIM * H_DIM * W_DIM)           // 1,048,576 = 2^20
#define NTHREADS_TOTAL (N_TOTAL / 4 / 8)          // 1,048,576 threads
#define QSTRIDE (N_TOTAL / 4 / 8)                 // 2^20 float4 stride

__global__ __launch_bounds__(256)
void pe_add_kernel(const float* __restrict__ x,
                   const float* __restrict__ Wt,
                   const float* __restrict__ bias,
                   float* __restrict__ out)
{
    const int gid = blockIdx.x * 256 + threadIdx.x;   // 0 .. 2^20-1

    // Element index of this thread's first float4; pe depends only on
    // t mod 2^20, which is invariant under the 4*2^20-element stride.
    const int t  = gid << 2;
    const int tm = t & (M_BATCH - 1);
    const int i  = tm >> 14;           // row
    const int j  = (tm >> 8) & 63;     // col
    const int c  = t & 255;            // channel base (multiple of 4)

    const float inv63 = 1.0f / 63.0f;
    const float u  = (float)j * inv63;
    const float v  = (float)i * inv63;
    const float mu = 1.0f - u;
    const float mv = 1.0f - v;

    // W rows c..c+3 are 16B-aligned float4s; bias c..c+3 likewise.
    const float4* W4 = reinterpret_cast<const float4*>(Wt);
    const float4  bb = reinterpret_cast<const float4*>(bias)[c >> 2];

    float4 pe;
    {
        const float4 w0 = W4[c + 0];
        const float4 w1 = W4[c + 1];
        const float4 w2 = W4[c + 2];
        const float4 w3 = W4[c + 3];
        pe.x = fmaf(w0.x, u, fmaf(w0.y, v, fmaf(w0.z, mu, fmaf(w0.w, mv, bb.x))));
        pe.y = fmaf(w1.x, u, fmaf(w1.y, v, fmaf(w1.z, mu, fmaf(w1.w, mv, bb.y))));
        pe.z = fmaf(w2.x, u, fmaf(w2.y, v, fmaf(w2.z, mu, fmaf(w2.w, mv, bb.z))));
        pe.w = fmaf(w3.x, u, fmaf(w3.y, v, fmaf(w3.z, mu, fmaf(w3.w, mv, bb.w))));
    }

    const float4* __restrict__ x4 = reinterpret_cast<const float4*>(x);
    float4* __restrict__ o4 = reinterpret_cast<float4*>(out);

    // 8 iterations, no bounds check (N/4 = 8 * 2^20 exactly).
    // Two batches of 4: 4 independent LDG.128 in flight, then 4 STG.128.
    #pragma unroll
    for (int half = 0; half < 2; half++) {
        const int base = gid + half * 4 * QSTRIDE;
        float4 xv[4];
        #pragma unroll
        for (int k = 0; k < 4; k++)
            xv[k] = __ldcs(&x4[base + k * QSTRIDE]);
        #pragma unroll
        for (int k = 0; k < 4; k++) {
            float4 o;
            o.x = xv[k].x + pe.x;
            o.y = xv[k].y + pe.y;
            o.z = xv[k].z + pe.z;
            o.w = xv[k].w + pe.w;
            __stcs(&o4[base + k * QSTRIDE], o);
        }
    }
}

extern "C" void kernel_launch(void* const* d_in, const int* in_sizes, int n_in,
                              void* d_out, int out_size)
{
    const float* x  = (const float*)d_in[0];   // [32,256,64,64]
    const float* Wt = (const float*)d_in[1];   // [256,4]
    const float* b  = (const float*)d_in[2];   // [256]
    float* out = (float*)d_out;

    (void)in_sizes; (void)n_in; (void)out_size;

    // 4096 blocks x 256 threads = 2^20 threads, 8 float4s each.
    pe_add_kernel<<<4096, 256>>>(x, Wt, b, out);
}